// round 1
// baseline (speedup 1.0000x reference)
#include <cuda_runtime.h>

// Problem constants
#define KI     9
#define KO     3
#define C_IN   3
#define H_IN   192
#define W_IN   192
#define B2     16               // B*L
#define HP     184              // H_IN - KI + 1  (unfold positions per axis)
#define OUT_H  186              // H_IN - 2*CUT, CUT = 3
#define WIDTH  50
#define WP     52               // WIDTH padded to multiple of 4 (float4 rows)
#define IN_DIM 243              // C_IN*KI*KI
#define TILE   16
#define XT     24               // TILE + KI - 1
#define XTP    25               // padded row stride for input tile
#define TILES  12               // ceil(HP / TILE)

// Scratch: per-position MLP outputs, plane-major [o][b2][py][px]
__device__ float g_y[9 * B2 * HP * HP];

__global__ __launch_bounds__(256, 2) void mlp_kernel(
    const float* __restrict__ x,
    const float* __restrict__ W1, const float* __restrict__ b1,
    const float* __restrict__ W2, const float* __restrict__ b2,
    const float* __restrict__ W3, const float* __restrict__ b3)
{
    extern __shared__ float smem[];
    float* sW1 = smem;                       // [243][52]
    float* sW2 = sW1 + IN_DIM * WP;          // [50][52]
    float* sW3 = sW2 + WIDTH * WP;           // [50][12]
    float* sb1 = sW3 + WIDTH * 12;           // [52]
    float* sb2 = sb1 + WP;                   // [52]
    float* sb3 = sb2 + WP;                   // [12]
    float* sx  = sb3 + 12;                   // [3][24][25]
    int*   ktab = (int*)(sx + C_IN * XT * XTP); // [243]

    const int tid = threadIdx.x;

    // ---- load W1 transposed: sW1[k][j] = W1[j][k], rows padded to 52 ----
    for (int idx = tid; idx < WIDTH * IN_DIM; idx += 256) {
        int j = idx / IN_DIM, k = idx - j * IN_DIM;
        sW1[k * WP + j] = W1[idx];
    }
    for (int k = tid; k < IN_DIM; k += 256) {
        sW1[k * WP + 50] = 0.f; sW1[k * WP + 51] = 0.f;
    }
    // ---- W2 transposed ----
    for (int idx = tid; idx < WIDTH * WIDTH; idx += 256) {
        int j = idx / WIDTH, k = idx - j * WIDTH;
        sW2[k * WP + j] = W2[idx];
    }
    for (int k = tid; k < WIDTH; k += 256) {
        sW2[k * WP + 50] = 0.f; sW2[k * WP + 51] = 0.f;
    }
    // ---- W3 transposed: sW3[k][o], rows padded to 12 ----
    for (int idx = tid; idx < 9 * WIDTH; idx += 256) {
        int o = idx / WIDTH, k = idx - o * WIDTH;
        sW3[k * 12 + o] = W3[idx];
    }
    for (int k = tid; k < WIDTH; k += 256) {
        sW3[k * 12 + 9] = 0.f; sW3[k * 12 + 10] = 0.f; sW3[k * 12 + 11] = 0.f;
    }
    if (tid < WP) sb1[tid] = (tid < WIDTH) ? b1[tid] : 0.f;
    if (tid < WP) sb2[tid] = (tid < WIDTH) ? b2[tid] : 0.f;
    if (tid < 12) sb3[tid] = (tid < 9) ? b3[tid] : 0.f;

    // ---- feature-k -> input tile offset table (keeps layer-1 loop dynamic/small) ----
    for (int k = tid; k < IN_DIM; k += 256) {
        int c = k / 81, r = k - c * 81;
        int di = r / 9, dj = r - di * 9;
        ktab[k] = (c * XT + di) * XTP + dj;
    }

    // ---- load input tile with halo ----
    const int b   = blockIdx.z;
    const int py0 = blockIdx.y * TILE;
    const int px0 = blockIdx.x * TILE;
    const float* xb = x + (size_t)b * (C_IN * H_IN * W_IN);
    for (int idx = tid; idx < C_IN * XT * XT; idx += 256) {
        int c = idx / (XT * XT);
        int r = (idx / XT) % XT;
        int q = idx % XT;
        int gy = py0 + r, gx = px0 + q;
        float v = 0.f;
        if (gy < H_IN && gx < W_IN) v = xb[(c * H_IN + gy) * W_IN + gx];
        sx[(c * XT + r) * XTP + q] = v;
    }
    __syncthreads();

    const int tx = tid & (TILE - 1);
    const int ty = tid >> 4;
    const int py = py0 + ty, px = px0 + tx;
    if (py >= HP || px >= HP) return;   // no further __syncthreads below

    const int base = ty * XTP + tx;

    // ---------------- layer 1: 243 -> 50 (+relu) ----------------
    float h1[WP];
    {
        const float4* bb = (const float4*)sb1;
        #pragma unroll
        for (int i = 0; i < 13; i++) {
            float4 v = bb[i];
            h1[4*i+0] = v.x; h1[4*i+1] = v.y; h1[4*i+2] = v.z; h1[4*i+3] = v.w;
        }
    }
    for (int k = 0; k < IN_DIM; k++) {
        float f = sx[ktab[k] + base];
        const float4* w = (const float4*)(sW1 + k * WP);
        #pragma unroll
        for (int i = 0; i < 13; i++) {
            float4 wv = w[i];
            h1[4*i+0] += f * wv.x;
            h1[4*i+1] += f * wv.y;
            h1[4*i+2] += f * wv.z;
            h1[4*i+3] += f * wv.w;
        }
    }
    #pragma unroll
    for (int i = 0; i < WP; i++) h1[i] = fmaxf(h1[i], 0.f);

    // ---------------- layer 2: 50 -> 50 (+relu) ----------------
    float h2[WP];
    {
        const float4* bb = (const float4*)sb2;
        #pragma unroll
        for (int i = 0; i < 13; i++) {
            float4 v = bb[i];
            h2[4*i+0] = v.x; h2[4*i+1] = v.y; h2[4*i+2] = v.z; h2[4*i+3] = v.w;
        }
    }
    #pragma unroll
    for (int k = 0; k < WIDTH; k++) {
        float f = h1[k];
        const float4* w = (const float4*)(sW2 + k * WP);
        #pragma unroll
        for (int i = 0; i < 13; i++) {
            float4 wv = w[i];
            h2[4*i+0] += f * wv.x;
            h2[4*i+1] += f * wv.y;
            h2[4*i+2] += f * wv.z;
            h2[4*i+3] += f * wv.w;
        }
    }
    #pragma unroll
    for (int i = 0; i < WP; i++) h2[i] = fmaxf(h2[i], 0.f);

    // ---------------- layer 3: 50 -> 9 ----------------
    float y[12];
    {
        const float4* bb = (const float4*)sb3;
        #pragma unroll
        for (int i = 0; i < 3; i++) {
            float4 v = bb[i];
            y[4*i+0] = v.x; y[4*i+1] = v.y; y[4*i+2] = v.z; y[4*i+3] = v.w;
        }
    }
    #pragma unroll
    for (int k = 0; k < WIDTH; k++) {
        float f = h2[k];
        const float4* w = (const float4*)(sW3 + k * 12);
        #pragma unroll
        for (int i = 0; i < 3; i++) {
            float4 wv = w[i];
            y[4*i+0] += f * wv.x;
            y[4*i+1] += f * wv.y;
            y[4*i+2] += f * wv.z;
            y[4*i+3] += f * wv.w;
        }
    }

    // ---- store per-position outputs, plane-major for coalesced fold gather ----
    const int ppos = py * HP + px;
    #pragma unroll
    for (int o = 0; o < 9; o++) {
        g_y[(o * B2 + b) * (HP * HP) + ppos] = y[o];
    }
}

// Fold (overlap-add + divisor) as a pure gather: out[b][oi][oj]
__global__ __launch_bounds__(256) void fold_kernel(float* __restrict__ out)
{
    int idx = blockIdx.x * blockDim.x + threadIdx.x;
    const int total = B2 * OUT_H * OUT_H;
    if (idx >= total) return;
    int oj = idx % OUT_H;
    int t  = idx / OUT_H;
    int oi = t % OUT_H;
    int b  = t / OUT_H;

    float acc = 0.f;
    int cnt = 0;
    #pragma unroll
    for (int di = 0; di < KO; di++) {
        int pi = oi - di;
        if (pi < 0 || pi >= HP) continue;
        #pragma unroll
        for (int dj = 0; dj < KO; dj++) {
            int pj = oj - dj;
            if (pj < 0 || pj >= HP) continue;
            acc += g_y[((di * KO + dj) * B2 + b) * (HP * HP) + pi * HP + pj];
            cnt++;
        }
    }
    out[idx] = acc / (float)cnt;
}

extern "C" void kernel_launch(void* const* d_in, const int* in_sizes, int n_in,
                              void* d_out, int out_size)
{
    const float* x  = (const float*)d_in[0];
    const float* W1 = (const float*)d_in[1];
    const float* b1 = (const float*)d_in[2];
    const float* W2 = (const float*)d_in[3];
    const float* b2 = (const float*)d_in[4];
    const float* W3 = (const float*)d_in[5];
    const float* b3 = (const float*)d_in[6];
    float* out = (float*)d_out;

    // dynamic smem: W1t + W2t + W3t + biases + input tile + ktab
    const int smem_words = IN_DIM * WP + WIDTH * WP + WIDTH * 12
                         + WP + WP + 12 + C_IN * XT * XTP + IN_DIM;
    const int smem_bytes = smem_words * 4;   // ~72 KB
    cudaFuncSetAttribute(mlp_kernel,
                         cudaFuncAttributeMaxDynamicSharedMemorySize, smem_bytes);

    dim3 grid(TILES, TILES, B2);
    mlp_kernel<<<grid, 256, smem_bytes>>>(x, W1, b1, W2, b2, W3, b3);

    const int total = B2 * OUT_H * OUT_H;
    fold_kernel<<<(total + 255) / 256, 256>>>(out);
}

// round 2
// speedup vs baseline: 1.1483x; 1.1483x over previous
#include <cuda_runtime.h>

// Problem constants
#define KI     9
#define KO     3
#define C_IN   3
#define H_IN   192
#define W_IN   192
#define B2     16               // B*L
#define HP     184              // H_IN - KI + 1
#define OUT_H  186
#define WIDTH  50
#define WP     52               // WIDTH padded to multiple of 4
#define IN_DIM 243
#define TILE   16
#define XT     24               // TILE + KI - 1
#define XTP    25               // padded row stride for input tile
#define TILES  12

// Scratch: per-position MLP outputs, plane-major [o][b2][py][px]
__device__ float g_y[9 * B2 * HP * HP];

// ---- packed fp32x2 helpers (sm_100+) ----
__device__ __forceinline__ void fma2(unsigned long long& d,
                                     unsigned long long a,
                                     unsigned long long b) {
    asm("fma.rn.f32x2 %0, %1, %2, %0;" : "+l"(d) : "l"(a), "l"(b));
}
__device__ __forceinline__ unsigned long long pack2(float f) {
    unsigned long long r;
    asm("mov.b64 %0, {%1, %1};" : "=l"(r) : "f"(f));
    return r;
}
__device__ __forceinline__ float2 unpack2(unsigned long long v) {
    float2 r;
    asm("mov.b64 {%0, %1}, %2;" : "=f"(r.x), "=f"(r.y) : "l"(v));
    return r;
}

__global__ __launch_bounds__(256, 2) void mlp_kernel(
    const float* __restrict__ x,
    const float* __restrict__ W1, const float* __restrict__ b1,
    const float* __restrict__ W2, const float* __restrict__ b2,
    const float* __restrict__ W3, const float* __restrict__ b3)
{
    extern __shared__ float smem[];
    float* sW1 = smem;                       // [243][52]  (transposed, padded)
    float* sW2 = sW1 + IN_DIM * WP;          // [50][52]
    float* sW3 = sW2 + WIDTH * WP;           // [50][12]
    float* sb1 = sW3 + WIDTH * 12;           // [52]
    float* sb2 = sb1 + WP;                   // [52]
    float* sb3 = sb2 + WP;                   // [12]
    float* sx  = sb3 + 12;                   // [3][24][25]

    const int tid = threadIdx.x;

    for (int idx = tid; idx < WIDTH * IN_DIM; idx += 256) {
        int j = idx / IN_DIM, k = idx - j * IN_DIM;
        sW1[k * WP + j] = W1[idx];
    }
    for (int k = tid; k < IN_DIM; k += 256) {
        sW1[k * WP + 50] = 0.f; sW1[k * WP + 51] = 0.f;
    }
    for (int idx = tid; idx < WIDTH * WIDTH; idx += 256) {
        int j = idx / WIDTH, k = idx - j * WIDTH;
        sW2[k * WP + j] = W2[idx];
    }
    for (int k = tid; k < WIDTH; k += 256) {
        sW2[k * WP + 50] = 0.f; sW2[k * WP + 51] = 0.f;
    }
    for (int idx = tid; idx < 9 * WIDTH; idx += 256) {
        int o = idx / WIDTH, k = idx - o * WIDTH;
        sW3[k * 12 + o] = W3[idx];
    }
    for (int k = tid; k < WIDTH; k += 256) {
        sW3[k * 12 + 9] = 0.f; sW3[k * 12 + 10] = 0.f; sW3[k * 12 + 11] = 0.f;
    }
    if (tid < WP) sb1[tid] = (tid < WIDTH) ? b1[tid] : 0.f;
    if (tid < WP) sb2[tid] = (tid < WIDTH) ? b2[tid] : 0.f;
    if (tid < 12) sb3[tid] = (tid < 9) ? b3[tid] : 0.f;

    const int b   = blockIdx.z;
    const int py0 = blockIdx.y * TILE;
    const int px0 = blockIdx.x * TILE;
    const float* xb = x + (size_t)b * (C_IN * H_IN * W_IN);
    for (int idx = tid; idx < C_IN * XT * XT; idx += 256) {
        int c = idx / (XT * XT);
        int r = (idx / XT) % XT;
        int q = idx % XT;
        int gy = py0 + r, gx = px0 + q;
        float v = 0.f;
        if (gy < H_IN && gx < W_IN) v = xb[(c * H_IN + gy) * W_IN + gx];
        sx[(c * XT + r) * XTP + q] = v;
    }
    __syncthreads();

    const int tx = tid & (TILE - 1);
    const int ty = tid >> 4;
    const int py = py0 + ty, px = px0 + tx;
    if (py >= HP || px >= HP) return;   // no __syncthreads past this point

    const int base = ty * XTP + tx;

    // ---------------- layer 1: 243 -> 50 (+relu), packed accumulators ----
    unsigned long long h1p[26];
    {
        const ulonglong2* bb = (const ulonglong2*)sb1;
        #pragma unroll
        for (int i = 0; i < 13; i++) {
            ulonglong2 v = bb[i];
            h1p[2*i] = v.x; h1p[2*i+1] = v.y;
        }
    }
    {
        const float* wrow = sW1;                    // advances 52 floats per k
        for (int c = 0; c < C_IN; c++) {
            for (int di = 0; di < KI; di++) {
                const float* frow = sx + (c * XT + di) * XTP + base;
                #pragma unroll
                for (int dj = 0; dj < KI; dj++) {
                    unsigned long long f = pack2(frow[dj]);
                    const ulonglong2* w = (const ulonglong2*)wrow;
                    #pragma unroll
                    for (int i = 0; i < 13; i++) {
                        ulonglong2 wv = w[i];
                        fma2(h1p[2*i],   f, wv.x);
                        fma2(h1p[2*i+1], f, wv.y);
                    }
                    wrow += WP;
                }
            }
        }
    }

    // ---------------- layer 2: 50 -> 50 (+relu) ----------------
    unsigned long long h2p[26];
    {
        const ulonglong2* bb = (const ulonglong2*)sb2;
        #pragma unroll
        for (int i = 0; i < 13; i++) {
            ulonglong2 v = bb[i];
            h2p[2*i] = v.x; h2p[2*i+1] = v.y;
        }
    }
    #pragma unroll
    for (int k = 0; k < WIDTH; k += 2) {
        float2 p = unpack2(h1p[k >> 1]);            // relu applied at extraction
        {
            unsigned long long f = pack2(fmaxf(p.x, 0.f));
            const ulonglong2* w = (const ulonglong2*)(sW2 + k * WP);
            #pragma unroll
            for (int i = 0; i < 13; i++) {
                ulonglong2 wv = w[i];
                fma2(h2p[2*i],   f, wv.x);
                fma2(h2p[2*i+1], f, wv.y);
            }
        }
        {
            unsigned long long f = pack2(fmaxf(p.y, 0.f));
            const ulonglong2* w = (const ulonglong2*)(sW2 + (k + 1) * WP);
            #pragma unroll
            for (int i = 0; i < 13; i++) {
                ulonglong2 wv = w[i];
                fma2(h2p[2*i],   f, wv.x);
                fma2(h2p[2*i+1], f, wv.y);
            }
        }
    }

    // ---------------- layer 3: 50 -> 9 ----------------
    unsigned long long yp[6];
    {
        const ulonglong2* bb = (const ulonglong2*)sb3;
        #pragma unroll
        for (int i = 0; i < 3; i++) {
            ulonglong2 v = bb[i];
            yp[2*i] = v.x; yp[2*i+1] = v.y;
        }
    }
    #pragma unroll
    for (int k = 0; k < WIDTH; k += 2) {
        float2 p = unpack2(h2p[k >> 1]);
        {
            unsigned long long f = pack2(fmaxf(p.x, 0.f));
            const ulonglong2* w = (const ulonglong2*)(sW3 + k * 12);
            #pragma unroll
            for (int i = 0; i < 3; i++) {
                ulonglong2 wv = w[i];
                fma2(yp[2*i],   f, wv.x);
                fma2(yp[2*i+1], f, wv.y);
            }
        }
        {
            unsigned long long f = pack2(fmaxf(p.y, 0.f));
            const ulonglong2* w = (const ulonglong2*)(sW3 + (k + 1) * 12);
            #pragma unroll
            for (int i = 0; i < 3; i++) {
                ulonglong2 wv = w[i];
                fma2(yp[2*i],   f, wv.x);
                fma2(yp[2*i+1], f, wv.y);
            }
        }
    }

    // ---- store per-position outputs, plane-major for coalesced fold gather ----
    const int ppos = py * HP + px;
    float yv[12];
    #pragma unroll
    for (int i = 0; i < 6; i++) {
        float2 p = unpack2(yp[i]);
        yv[2*i] = p.x; yv[2*i+1] = p.y;
    }
    #pragma unroll
    for (int o = 0; o < 9; o++) {
        g_y[(o * B2 + b) * (HP * HP) + ppos] = yv[o];
    }
}

// Fold (overlap-add + divisor) as a pure gather: out[b][oi][oj]
__global__ __launch_bounds__(256) void fold_kernel(float* __restrict__ out)
{
    int idx = blockIdx.x * blockDim.x + threadIdx.x;
    const int total = B2 * OUT_H * OUT_H;
    if (idx >= total) return;
    int oj = idx % OUT_H;
    int t  = idx / OUT_H;
    int oi = t % OUT_H;
    int b  = t / OUT_H;

    float acc = 0.f;
    int cnt = 0;
    #pragma unroll
    for (int di = 0; di < KO; di++) {
        int pi = oi - di;
        if (pi < 0 || pi >= HP) continue;
        #pragma unroll
        for (int dj = 0; dj < KO; dj++) {
            int pj = oj - dj;
            if (pj < 0 || pj >= HP) continue;
            acc += g_y[((di * KO + dj) * B2 + b) * (HP * HP) + pi * HP + pj];
            cnt++;
        }
    }
    out[idx] = acc / (float)cnt;
}

extern "C" void kernel_launch(void* const* d_in, const int* in_sizes, int n_in,
                              void* d_out, int out_size)
{
    const float* x  = (const float*)d_in[0];
    const float* W1 = (const float*)d_in[1];
    const float* b1 = (const float*)d_in[2];
    const float* W2 = (const float*)d_in[3];
    const float* b2 = (const float*)d_in[4];
    const float* W3 = (const float*)d_in[5];
    const float* b3 = (const float*)d_in[6];
    float* out = (float*)d_out;

    const int smem_words = IN_DIM * WP + WIDTH * WP + WIDTH * 12
                         + WP + WP + 12 + C_IN * XT * XTP;
    const int smem_bytes = smem_words * 4;   // ~71 KB
    cudaFuncSetAttribute(mlp_kernel,
                         cudaFuncAttributeMaxDynamicSharedMemorySize, smem_bytes);

    dim3 grid(TILES, TILES, B2);
    mlp_kernel<<<grid, 256, smem_bytes>>>(x, W1, b1, W2, b2, W3, b3);

    const int total = B2 * OUT_H * OUT_H;
    fold_kernel<<<(total + 255) / 256, 256>>>(out);
}